// round 13
// baseline (speedup 1.0000x reference)
#include <cuda_runtime.h>
#include <cuda_bf16.h>

#define N_NODES   4000000
#define N_GRAPHS  4096
#define D_FEAT    8
#define N_CLASSES 10
#define SEGS_PER_BLOCK 8
#define N_BLOCKS (N_GRAPHS / SEGS_PER_BLOCK)   // 512
#define FULL 0xFFFFFFFFu

// batch_ids may be int64 OR int32 (JAX under default x64=False silently makes
// them int32). Values < 4096, so for int64 data every high word is 0: viewing
// the buffer as int32, element N_NODES-1 is an int64 high word (==0) or the
// max sorted int32 id (>0).
__device__ __forceinline__ int id_at(const int* __restrict__ ids32, bool is64, int i) {
    return is64 ? ids32[2 * i] : ids32[i];
}

// Half-warp cooperative 16-ary lower_bound of v over sorted ids in [lo, hi).
__device__ __forceinline__ int kary_lower_bound(
    const int* __restrict__ ids32, bool is64, int v,
    int lo, int hi, int sub, int half_shift)
{
    const unsigned hmask = 0xFFFFu << half_shift;
    while (hi - lo > 16) {
        const int range = hi - lo;
        const int pos = lo + (int)(((long long)range * (sub + 1)) >> 4);
        const bool less = id_at(ids32, is64, pos - 1) < v;
        const unsigned ball = __ballot_sync(hmask, less);
        const int cnt = __popc((ball >> half_shift) & 0xFFFFu);
        const int nlo = lo + (int)(((long long)range * cnt) >> 4);
        const int nhi = (cnt == 16) ? hi
                      : lo + (int)(((long long)range * (cnt + 1)) >> 4);
        lo = nlo; hi = nhi;
    }
    const int pos = lo + sub;
    const bool less = (pos < hi) ? (id_at(ids32, is64, pos) < v) : false;
    const unsigned ball = __ballot_sync(hmask, less);
    return lo + __popc((ball >> half_shift) & 0xFFFFu);
}

__device__ __forceinline__ void flush_acc(float* srow, int colbase, float4 a) {
    atomicAdd(srow + colbase + 0, a.x);
    atomicAdd(srow + colbase + 1, a.y);
    atomicAdd(srow + colbase + 2, a.z);
    atomicAdd(srow + colbase + 3, a.w);
}

// Block-cooperative: 256 threads stream ONE contiguous range covering 8
// segments (512 chip-wide streams instead of 4096 -> DRAM row locality).
__global__ __launch_bounds__(256) void fused_pool_gemm_kernel(
    const float4* __restrict__ x4,
    const int*    __restrict__ ids32,
    const float*  __restrict__ W,      // [10, 8]
    const float*  __restrict__ b,      // [10]
    float*        __restrict__ out)    // [4096, 10]
{
    __shared__ int   sb[SEGS_PER_BLOCK + 1];           // row starts
    __shared__ float ssum[SEGS_PER_BLOCK][D_FEAT];

    const int tid  = threadIdx.x;
    const int warp = tid >> 5;
    const int lane = tid & 31;
    const int g0   = blockIdx.x * SEGS_PER_BLOCK;

    if (tid < SEGS_PER_BLOCK * D_FEAT)
        ssum[tid >> 3][tid & 7] = 0.0f;

    // ---- Phase 1: warps 0-4 search the 9 boundaries (2 per warp) ----
    if (warp < 5) {
        const bool is64 = (ids32[N_NODES - 1] == 0);
        const int half_shift = lane & 16;
        const int sub  = lane & 15;
        const int bidx = 2 * warp + (half_shift ? 1 : 0);   // 0..9
        const int v    = g0 + bidx;

        int res;
        if (v >= N_GRAPHS) {
            res = N_NODES;
        } else {
            // +-8192 window (>=8 sd of binomial start position);
            // bracket-verified with full-range fallback.
            const long long approx = ((long long)v * N_NODES) >> 12;
            int lo = (int)(approx - 8192); if (lo < 0) lo = 0;
            int hi = (int)(approx + 8192); if (hi > N_NODES) hi = N_NODES;
            const bool ok_lo = (lo == 0)       || (id_at(ids32, is64, lo - 1) < v);
            const bool ok_hi = (hi == N_NODES) || (id_at(ids32, is64, hi) >= v);
            if (!(ok_lo && ok_hi)) { lo = 0; hi = N_NODES; }
            res = kary_lower_bound(ids32, is64, v, lo, hi, sub, half_shift);
        }
        if (((lane & 15) == 0) && bidx <= SEGS_PER_BLOCK)
            sb[bidx] = res;
    }
    __syncthreads();

    // ---- Phase 2: single contiguous block stream with running (seg, acc) ----
    const int row0  = sb[0];
    const long long base = (long long)row0 * 2;     // float4 units (even)
    const int total = (sb[SEGS_PER_BLOCK] - row0) * 2;
    const int colbase = (tid & 1) * 4;              // parity -> cols 0-3 / 4-7

    int s = 0;
    int end2 = (sb[1] - row0) * 2;                  // cached seg end (f4 units)
    float4 acc = make_float4(0.f, 0.f, 0.f, 0.f);

    int c = 0;
    while (c + 2048 <= total) {       // 8 loads x 256 threads = 32 KB contiguous
        const long long p = base + c + tid;
        float4 v0 = __ldg(&x4[p       ]);
        float4 v1 = __ldg(&x4[p +  256]);
        float4 v2 = __ldg(&x4[p +  512]);
        float4 v3 = __ldg(&x4[p +  768]);
        float4 v4 = __ldg(&x4[p + 1024]);
        float4 v5 = __ldg(&x4[p + 1280]);
        float4 v6 = __ldg(&x4[p + 1536]);
        float4 v7 = __ldg(&x4[p + 1792]);

        #pragma unroll
        for (int k = 0; k < 8; k++) {
            const int j = c + tid + k * 256;
            if (j >= end2) {           // boundary crossed: flush + advance
                flush_acc(&ssum[s][0], colbase, acc);
                acc = make_float4(0.f, 0.f, 0.f, 0.f);
                do { s++; end2 = (sb[s + 1] - row0) * 2; } while (j >= end2);
            }
            const float4 vv = (k == 0) ? v0 : (k == 1) ? v1 : (k == 2) ? v2 :
                              (k == 3) ? v3 : (k == 4) ? v4 : (k == 5) ? v5 :
                              (k == 6) ? v6 : v7;
            acc.x += vv.x; acc.y += vv.y; acc.z += vv.z; acc.w += vv.w;
        }
        c += 2048;
    }
    for (int j = c + tid; j < total; j += 256) {    // tail
        const float4 vv = __ldg(&x4[base + j]);
        if (j >= end2) {
            flush_acc(&ssum[s][0], colbase, acc);
            acc = make_float4(0.f, 0.f, 0.f, 0.f);
            do { s++; end2 = (sb[s + 1] - row0) * 2; } while (j >= end2);
        }
        acc.x += vv.x; acc.y += vv.y; acc.z += vv.z; acc.w += vv.w;
    }
    flush_acc(&ssum[s][0], colbase, acc);
    __syncthreads();

    // ---- Phase 3: warp w finalizes segment g0+w (mean + tiny GEMM) ----
    {
        const int g   = g0 + warp;
        const int cnt = sb[warp + 1] - sb[warp];
        const float inv = (cnt > 0) ? (1.0f / (float)cnt) : 0.0f;
        if (lane < N_CLASSES) {
            const float* w = W + lane * D_FEAT;
            float r = __ldg(&b[lane]);
            #pragma unroll
            for (int k = 0; k < D_FEAT; k++)
                r += ssum[warp][k] * inv * __ldg(&w[k]);
            out[g * N_CLASSES + lane] = r;
        }
    }
}

extern "C" void kernel_launch(void* const* d_in, const int* in_sizes, int n_in,
                              void* d_out, int out_size) {
    // Bind inputs by element count (robust to metadata ordering):
    //   x: 32,000,000 f32 | batch_ids: 4,000,000 | W: 80 | b: 10
    const float* x   = nullptr;
    const void*  ids = nullptr;
    const float* W   = nullptr;
    const float* b   = nullptr;
    for (int i = 0; i < n_in; i++) {
        switch (in_sizes[i]) {
            case N_NODES * D_FEAT:   x   = (const float*)d_in[i]; break;
            case N_NODES:            ids = d_in[i];               break;
            case N_CLASSES * D_FEAT: W   = (const float*)d_in[i]; break;
            case N_CLASSES:          b   = (const float*)d_in[i]; break;
            default: break; // input_ids / attention_mask: unused
        }
    }
    float* out = (float*)d_out;

    fused_pool_gemm_kernel<<<N_BLOCKS, 256>>>(
        (const float4*)x, (const int*)ids, W, b, out);
}

// round 14
// speedup vs baseline: 2.3543x; 2.3543x over previous
#include <cuda_runtime.h>
#include <cuda_bf16.h>

#define N_NODES   4000000
#define N_GRAPHS  4096
#define D_FEAT    8
#define N_CLASSES 10
#define WARPS_PER_BLOCK 8
#define N_BLOCKS (N_GRAPHS / WARPS_PER_BLOCK)   // 512
#define FULL 0xFFFFFFFFu

__device__ int g_seg_start[N_GRAPHS + 1];

// batch_ids may be int64 OR int32 (JAX under default x64=False silently makes
// them int32). Values < 4096, so for int64 data every high word is 0: viewing
// the buffer as int32, element N_NODES-1 is an int64 high word (==0) or the
// max sorted int32 id (>0).
__device__ __forceinline__ int id_at(const int* __restrict__ ids32, bool is64, int i) {
    return is64 ? ids32[2 * i] : ids32[i];
}

// Half-warp cooperative 16-ary lower_bound of v over sorted ids in [lo, hi).
__device__ __forceinline__ int kary_lower_bound(
    const int* __restrict__ ids32, bool is64, int v,
    int lo, int hi, int sub, int half_shift)
{
    const unsigned hmask = 0xFFFFu << half_shift;
    while (hi - lo > 16) {
        const int range = hi - lo;
        const int pos = lo + (int)(((long long)range * (sub + 1)) >> 4);
        const bool less = id_at(ids32, is64, pos - 1) < v;
        const unsigned ball = __ballot_sync(hmask, less);
        const int cnt = __popc((ball >> half_shift) & 0xFFFFu);
        const int nlo = lo + (int)(((long long)range * cnt) >> 4);
        const int nhi = (cnt == 16) ? hi
                      : lo + (int)(((long long)range * (cnt + 1)) >> 4);
        lo = nlo; hi = nhi;
    }
    const int pos = lo + sub;
    const bool less = (pos < hi) ? (id_at(ids32, is64, pos) < v) : false;
    const unsigned ball = __ballot_sync(hmask, less);
    return lo + __popc((ball >> half_shift) & 0xFFFFu);
}

// ---- Kernel A: fast bounds. Warp w resolves boundaries 2w (lower half-warp)
// and 2w+1 (upper half-warp) via windowed 16-ary search (~3 probe rounds).
__global__ __launch_bounds__(128) void bounds_kernel(const int* __restrict__ ids32) {
    const int wid  = (blockIdx.x * 128 + threadIdx.x) >> 5;
    const int lane = threadIdx.x & 31;
    const int half_shift = lane & 16;
    const int sub  = lane & 15;
    const int v    = 2 * wid + (half_shift ? 1 : 0);   // boundary value
    if (v > N_GRAPHS) return;

    int res;
    if (v >= N_GRAPHS) {
        res = N_NODES;
    } else {
        const bool is64 = (ids32[N_NODES - 1] == 0);
        // +-8192 window (>=8 sd of binomial start position); bracket-verified
        // with full-range fallback.
        const long long approx = ((long long)v * N_NODES) >> 12;
        int lo = (int)(approx - 8192); if (lo < 0) lo = 0;
        int hi = (int)(approx + 8192); if (hi > N_NODES) hi = N_NODES;
        const bool ok_lo = (lo == 0)       || (id_at(ids32, is64, lo - 1) < v);
        const bool ok_hi = (hi == N_NODES) || (id_at(ids32, is64, hi) >= v);
        if (!(ok_lo && ok_hi)) { lo = 0; hi = N_NODES; }
        res = kary_lower_bound(ids32, is64, v, lo, hi, sub, half_shift);
    }
    if ((lane & 15) == 0) g_seg_start[v] = res;
}

// ---- Kernel B: EXACT R2 pool+GEMM (best measured stream: 27.1 us) ----------
// One warp per segment, flat float4 stream (parity butterfly), fused GEMM.
__global__ __launch_bounds__(256) void pool_gemm_kernel(
    const float4* __restrict__ x4,
    const float*  __restrict__ W,   // [10, 8] row-major
    const float*  __restrict__ b,   // [10]
    float*        __restrict__ out) // [4096, 10]
{
    const int warp = threadIdx.x >> 5;
    const int lane = threadIdx.x & 31;
    const int g = blockIdx.x * WARPS_PER_BLOCK + warp;   // segment id

    const int start = __ldg(&g_seg_start[g]);
    const int end   = __ldg(&g_seg_start[g + 1]);
    const int cnt   = end - start;
    const long long base = (long long)start * 2;   // float4 units
    const int n4 = cnt * 2;

    float4 a0 = make_float4(0.f, 0.f, 0.f, 0.f);
    float4 a1 = make_float4(0.f, 0.f, 0.f, 0.f);

    int j = lane;
    while (j + 32 < n4) {
        float4 v0 = __ldg(&x4[base + j]);
        float4 v1 = __ldg(&x4[base + j + 32]);
        a0.x += v0.x; a0.y += v0.y; a0.z += v0.z; a0.w += v0.w;
        a1.x += v1.x; a1.y += v1.y; a1.z += v1.z; a1.w += v1.w;
        j += 64;
    }
    if (j < n4) {
        float4 v0 = __ldg(&x4[base + j]);
        a0.x += v0.x; a0.y += v0.y; a0.z += v0.z; a0.w += v0.w;
    }
    a0.x += a1.x; a0.y += a1.y; a0.z += a1.z; a0.w += a1.w;

    // Parity-preserving butterfly over masks 16,8,4,2: even lanes end with
    // full sums of cols 0-3, odd lanes cols 4-7.
    #pragma unroll
    for (int m = 16; m >= 2; m >>= 1) {
        a0.x += __shfl_xor_sync(FULL, a0.x, m);
        a0.y += __shfl_xor_sync(FULL, a0.y, m);
        a0.z += __shfl_xor_sync(FULL, a0.z, m);
        a0.w += __shfl_xor_sync(FULL, a0.w, m);
    }

    __shared__ float pooled[WARPS_PER_BLOCK][D_FEAT];
    const float inv = (cnt > 0) ? (1.0f / (float)cnt) : 0.0f;
    if (lane == 0) {
        pooled[warp][0] = a0.x * inv; pooled[warp][1] = a0.y * inv;
        pooled[warp][2] = a0.z * inv; pooled[warp][3] = a0.w * inv;
    } else if (lane == 1) {
        pooled[warp][4] = a0.x * inv; pooled[warp][5] = a0.y * inv;
        pooled[warp][6] = a0.z * inv; pooled[warp][7] = a0.w * inv;
    }
    __syncwarp(FULL);

    if (lane < N_CLASSES) {
        float acc = __ldg(&b[lane]);
        #pragma unroll
        for (int k = 0; k < D_FEAT; k++)
            acc += pooled[warp][k] * __ldg(&W[lane * D_FEAT + k]);
        out[(long long)g * N_CLASSES + lane] = acc;
    }
}

extern "C" void kernel_launch(void* const* d_in, const int* in_sizes, int n_in,
                              void* d_out, int out_size) {
    // Bind inputs by element count (robust to metadata ordering):
    //   x: 32,000,000 f32 | batch_ids: 4,000,000 | W: 80 | b: 10
    const float* x   = nullptr;
    const void*  ids = nullptr;
    const float* W   = nullptr;
    const float* b   = nullptr;
    for (int i = 0; i < n_in; i++) {
        switch (in_sizes[i]) {
            case N_NODES * D_FEAT:   x   = (const float*)d_in[i]; break;
            case N_NODES:            ids = d_in[i];               break;
            case N_CLASSES * D_FEAT: W   = (const float*)d_in[i]; break;
            case N_CLASSES:          b   = (const float*)d_in[i]; break;
            default: break; // input_ids / attention_mask: unused
        }
    }
    float* out = (float*)d_out;

    // 2049 warps needed for 4097 boundaries -> 513 blocks x 128 threads
    bounds_kernel<<<513, 128>>>((const int*)ids);
    pool_gemm_kernel<<<N_BLOCKS, 256>>>((const float4*)x, W, b, out);
}

// round 15
// speedup vs baseline: 2.5493x; 1.0828x over previous
#include <cuda_runtime.h>
#include <cuda_bf16.h>
#include <limits.h>

#define N_NODES   4000000
#define N_GRAPHS  4096
#define D_FEAT    8
#define N_CLASSES 10
#define WARPS_PER_BLOCK 4
#define N_BLOCKS (N_GRAPHS / WARPS_PER_BLOCK)   // 1024
#define FULL 0xFFFFFFFFu

// batch_ids may be int64 OR int32 (JAX under default x64=False silently makes
// them int32). Values < 4096, so for int64 data every high word is 0: viewing
// the buffer as int32, element N_NODES-1 is an int64 high word (==0) or the
// max sorted int32 id (>0).
__device__ __forceinline__ int id_at(const int* __restrict__ ids32, bool is64, int i) {
    return is64 ? ids32[2 * i] : ids32[i];
}

// One 16-ary refinement round over [lo, hi) for target v within a half-warp.
// Probe value is supplied (already loaded) so round 1 can overlap the bracket
// check. Returns new [lo, hi).
__device__ __forceinline__ void kary_round(
    int& lo, int& hi, bool less, unsigned hmask, int half_shift)
{
    const int range = hi - lo;
    const unsigned ball = __ballot_sync(hmask, less);
    const int cnt = __popc((ball >> half_shift) & 0xFFFFu);
    const int nlo = lo + (int)(((long long)range * cnt) >> 4);
    const int nhi = (cnt == 16) ? hi
                  : lo + (int)(((long long)range * (cnt + 1)) >> 4);
    lo = nlo; hi = nhi;
}

__device__ __forceinline__ int kary_probe_pos(int lo, int hi, int sub) {
    return lo + (int)(((long long)(hi - lo) * (sub + 1)) >> 4);   // in (lo, hi]
}

// Full k-ary lower_bound (used on the statistically-never fallback path).
__device__ __forceinline__ int kary_lower_bound(
    const int* __restrict__ ids32, bool is64, int v,
    int lo, int hi, int sub, int half_shift)
{
    const unsigned hmask = 0xFFFFu << half_shift;
    while (hi - lo > 16) {
        const int pos = kary_probe_pos(lo, hi, sub);
        const bool less = id_at(ids32, is64, pos - 1) < v;
        kary_round(lo, hi, less, hmask, half_shift);
    }
    const int pos = lo + sub;
    const bool less = (pos < hi) ? (id_at(ids32, is64, pos) < v) : false;
    const unsigned ball = __ballot_sync(hmask, less);
    return lo + __popc((ball >> half_shift) & 0xFFFFu);
}

#define ACC4(A, V) do { A.x += V.x; A.y += V.y; A.z += V.z; A.w += V.w; } while (0)

__global__ __launch_bounds__(128) void fused_pool_gemm_kernel(
    const float4* __restrict__ x4,
    const int*    __restrict__ ids32,
    const float*  __restrict__ W,      // [10, 8]
    const float*  __restrict__ b,      // [10]
    float*        __restrict__ out)    // [4096, 10]
{
    const int warp = threadIdx.x >> 5;
    const int lane = threadIdx.x & 31;
    const int g    = blockIdx.x * WARPS_PER_BLOCK + warp;   // segment id

    // ---- Phase 0: L2 prefetch of segment head; overlaps the search below ----
    {
        long long arow = ((long long)g * N_NODES) >> 12;
        if (arow > N_NODES - 512) arow = N_NODES - 512;
        const char* pbase = (const char*)x4 + arow * 32 + (long long)lane * 128;
        #pragma unroll
        for (int k = 0; k < 4; k++)
            asm volatile("prefetch.global.L2 [%0];" :: "l"(pbase + k * 4096));
    }

    // ---- Phase 1: per-warp cooperative boundary search ----
    // Bracket-check loads issue CONCURRENTLY with round-1 probes (all
    // independent) -> one fewer dependent latency on the critical path.
    const bool is64 = (ids32[N_NODES - 1] == 0);
    const int half_shift = lane & 16;
    const int sub = lane & 15;
    const unsigned hmask = 0xFFFFu << half_shift;
    const int v = (half_shift == 0) ? g : g + 1;   // lower half: start; upper: end

    int res;
    if (v >= N_GRAPHS) {
        res = N_NODES;
    } else {
        // +-8192 window (>=8 sd of the binomial start position).
        const long long approx = ((long long)v * N_NODES) >> 12;
        int lo = (int)(approx - 8192); if (lo < 0) lo = 0;
        int hi = (int)(approx + 8192); if (hi > N_NODES) hi = N_NODES;

        // Issue bracket loads + round-1 probe together.
        const int bl = (lo == 0)       ? INT_MIN : id_at(ids32, is64, lo - 1);
        const int bh = (hi == N_NODES) ? INT_MAX : id_at(ids32, is64, hi);
        const int pos1 = kary_probe_pos(lo, hi, sub);
        const bool less1 = id_at(ids32, is64, pos1 - 1) < v;

        if (bl < v && bh >= v) {            // bracket holds (statistically always)
            kary_round(lo, hi, less1, hmask, half_shift);   // fold round 1
            while (hi - lo > 16) {
                const int pos = kary_probe_pos(lo, hi, sub);
                const bool less = id_at(ids32, is64, pos - 1) < v;
                kary_round(lo, hi, less, hmask, half_shift);
            }
            const int pos = lo + sub;
            const bool less = (pos < hi) ? (id_at(ids32, is64, pos) < v) : false;
            const unsigned ball = __ballot_sync(hmask, less);
            res = lo + __popc((ball >> half_shift) & 0xFFFFu);
        } else {                            // correctness fallback: full range
            res = kary_lower_bound(ids32, is64, v, 0, N_NODES, sub, half_shift);
        }
    }
    __syncwarp(FULL);
    const int start = __shfl_sync(FULL, res, 0);
    const int end   = __shfl_sync(FULL, res, 16);
    const int cnt   = end - start;
    const long long base = (long long)start * 2;   // float4 units
    const int n4 = cnt * 2;

    // ---- Phase 2: float4 streaming reduction, unroll 8 + batch tail ----
    float4 acc0 = make_float4(0.f,0.f,0.f,0.f);
    float4 acc1 = make_float4(0.f,0.f,0.f,0.f);
    float4 acc2 = make_float4(0.f,0.f,0.f,0.f);
    float4 acc3 = make_float4(0.f,0.f,0.f,0.f);

    int c = 0;
    while (c + 256 <= n4) {
        const long long p = base + c + lane;
        float4 v0 = __ldg(&x4[p      ]);
        float4 v1 = __ldg(&x4[p +  32]);
        float4 v2 = __ldg(&x4[p +  64]);
        float4 v3 = __ldg(&x4[p +  96]);
        float4 v4 = __ldg(&x4[p + 128]);
        float4 v5 = __ldg(&x4[p + 160]);
        float4 v6 = __ldg(&x4[p + 192]);
        float4 v7 = __ldg(&x4[p + 224]);
        ACC4(acc0, v0); ACC4(acc1, v1); ACC4(acc2, v2); ACC4(acc3, v3);
        ACC4(acc0, v4); ACC4(acc1, v5); ACC4(acc2, v6); ACC4(acc3, v7);
        c += 256;
    }
    // Batch tail: up to 8 PREDICATED independent loads -> one dependency round
    // instead of a serialized 32-stride loop.
    {
        const long long p = base + c + lane;
        #pragma unroll
        for (int t = 0; t < 8; t++) {
            if (c + lane + t * 32 < n4) {
                float4 vv = __ldg(&x4[p + t * 32]);
                if (t & 1) { ACC4(acc1, vv); } else { ACC4(acc0, vv); }
            }
        }
    }
    acc0.x += acc1.x + acc2.x + acc3.x;
    acc0.y += acc1.y + acc2.y + acc3.y;
    acc0.z += acc1.z + acc2.z + acc3.z;
    acc0.w += acc1.w + acc2.w + acc3.w;

    // Parity-preserving butterfly: lane 0 -> cols 0-3, lane 1 -> cols 4-7.
    #pragma unroll
    for (int m = 16; m >= 2; m >>= 1) {
        acc0.x += __shfl_xor_sync(FULL, acc0.x, m);
        acc0.y += __shfl_xor_sync(FULL, acc0.y, m);
        acc0.z += __shfl_xor_sync(FULL, acc0.z, m);
        acc0.w += __shfl_xor_sync(FULL, acc0.w, m);
    }

    // ---- Phase 3: broadcast pooled vector via shuffles, fused tiny GEMM ----
    const float inv = (cnt > 0) ? (1.0f / (float)cnt) : 0.0f;
    const float p0 = __shfl_sync(FULL, acc0.x, 0) * inv;
    const float p1 = __shfl_sync(FULL, acc0.y, 0) * inv;
    const float p2 = __shfl_sync(FULL, acc0.z, 0) * inv;
    const float p3 = __shfl_sync(FULL, acc0.w, 0) * inv;
    const float p4 = __shfl_sync(FULL, acc0.x, 1) * inv;
    const float p5 = __shfl_sync(FULL, acc0.y, 1) * inv;
    const float p6 = __shfl_sync(FULL, acc0.z, 1) * inv;
    const float p7 = __shfl_sync(FULL, acc0.w, 1) * inv;

    if (lane < N_CLASSES) {
        const float* w = W + lane * D_FEAT;
        float r = __ldg(&b[lane]);
        r += p0 * __ldg(&w[0]) + p1 * __ldg(&w[1]) + p2 * __ldg(&w[2]) + p3 * __ldg(&w[3]);
        r += p4 * __ldg(&w[4]) + p5 * __ldg(&w[5]) + p6 * __ldg(&w[6]) + p7 * __ldg(&w[7]);
        out[g * N_CLASSES + lane] = r;
    }
}

extern "C" void kernel_launch(void* const* d_in, const int* in_sizes, int n_in,
                              void* d_out, int out_size) {
    // Bind inputs by element count (robust to metadata ordering):
    //   x: 32,000,000 f32 | batch_ids: 4,000,000 | W: 80 | b: 10
    const float* x   = nullptr;
    const void*  ids = nullptr;
    const float* W   = nullptr;
    const float* b   = nullptr;
    for (int i = 0; i < n_in; i++) {
        switch (in_sizes[i]) {
            case N_NODES * D_FEAT:   x   = (const float*)d_in[i]; break;
            case N_NODES:            ids = d_in[i];               break;
            case N_CLASSES * D_FEAT: W   = (const float*)d_in[i]; break;
            case N_CLASSES:          b   = (const float*)d_in[i]; break;
            default: break; // input_ids / attention_mask: unused
        }
    }
    float* out = (float*)d_out;

    fused_pool_gemm_kernel<<<N_BLOCKS, 128>>>(
        (const float4*)x, (const int*)ids, W, b, out);
}

// round 16
// speedup vs baseline: 3.7017x; 1.4521x over previous
#include <cuda_runtime.h>
#include <cuda_bf16.h>
#include <limits.h>

#define N_NODES   4000000
#define N_GRAPHS  4096
#define D_FEAT    8
#define N_CLASSES 10
#define WARPS_PER_BLOCK 4
#define N_BLOCKS (N_GRAPHS / WARPS_PER_BLOCK)   // 1024
#define FULL 0xFFFFFFFFu

// batch_ids may be int64 OR int32 (JAX under default x64=False silently makes
// them int32). Values < 4096, so for int64 data every high word is 0: viewing
// the buffer as int32, element N_NODES-1 is an int64 high word (==0) or the
// max sorted int32 id (>0).
__device__ __forceinline__ int id_at(const int* __restrict__ ids32, bool is64, int i) {
    return is64 ? ids32[2 * i] : ids32[i];
}

// Read-once stream load: non-coherent path, L1 no-allocate (data has zero
// reuse; skip L1 fill to reduce L1tex wavefront-queue pressure).
__device__ __forceinline__ float4 ldg_stream(const float4* __restrict__ p) {
    float4 v;
    asm volatile("ld.global.nc.L1::no_allocate.v4.f32 {%0,%1,%2,%3}, [%4];"
                 : "=f"(v.x), "=f"(v.y), "=f"(v.z), "=f"(v.w) : "l"(p));
    return v;
}

// One 16-ary refinement round over [lo, hi) for target v within a half-warp.
__device__ __forceinline__ void kary_round(
    int& lo, int& hi, bool less, unsigned hmask, int half_shift)
{
    const int range = hi - lo;
    const unsigned ball = __ballot_sync(hmask, less);
    const int cnt = __popc((ball >> half_shift) & 0xFFFFu);
    const int nlo = lo + (int)(((long long)range * cnt) >> 4);
    const int nhi = (cnt == 16) ? hi
                  : lo + (int)(((long long)range * (cnt + 1)) >> 4);
    lo = nlo; hi = nhi;
}

__device__ __forceinline__ int kary_probe_pos(int lo, int hi, int sub) {
    return lo + (int)(((long long)(hi - lo) * (sub + 1)) >> 4);   // in (lo, hi]
}

// Full k-ary lower_bound (statistically-never fallback path).
__device__ __forceinline__ int kary_lower_bound(
    const int* __restrict__ ids32, bool is64, int v,
    int lo, int hi, int sub, int half_shift)
{
    const unsigned hmask = 0xFFFFu << half_shift;
    while (hi - lo > 16) {
        const int pos = kary_probe_pos(lo, hi, sub);
        const bool less = id_at(ids32, is64, pos - 1) < v;
        kary_round(lo, hi, less, hmask, half_shift);
    }
    const int pos = lo + sub;
    const bool less = (pos < hi) ? (id_at(ids32, is64, pos) < v) : false;
    const unsigned ball = __ballot_sync(hmask, less);
    return lo + __popc((ball >> half_shift) & 0xFFFFu);
}

#define ACC4(A, V) do { A.x += V.x; A.y += V.y; A.z += V.z; A.w += V.w; } while (0)

__global__ __launch_bounds__(128) void fused_pool_gemm_kernel(
    const float4* __restrict__ x4,
    const int*    __restrict__ ids32,
    const float*  __restrict__ W,      // [10, 8]
    const float*  __restrict__ b,      // [10]
    float*        __restrict__ out)    // [4096, 10]
{
    const int warp = threadIdx.x >> 5;
    const int lane = threadIdx.x & 31;
    const int g    = blockIdx.x * WARPS_PER_BLOCK + warp;   // segment id

    // ---- Phase 0: L2 prefetch of segment head; overlaps the search below ----
    {
        long long arow = ((long long)g * N_NODES) >> 12;
        if (arow > N_NODES - 512) arow = N_NODES - 512;
        const char* pbase = (const char*)x4 + arow * 32 + (long long)lane * 128;
        #pragma unroll
        for (int k = 0; k < 4; k++)
            asm volatile("prefetch.global.L2 [%0];" :: "l"(pbase + k * 4096));
    }

    // ---- Phase 1: per-warp cooperative boundary search ----
    // Bracket-check loads issue CONCURRENTLY with round-1 probes.
    const bool is64 = (ids32[N_NODES - 1] == 0);
    const int half_shift = lane & 16;
    const int sub = lane & 15;
    const unsigned hmask = 0xFFFFu << half_shift;
    const int v = (half_shift == 0) ? g : g + 1;   // lower half: start; upper: end

    int res;
    if (v >= N_GRAPHS) {
        res = N_NODES;
    } else {
        // +-8192 window (>=8 sd of the binomial start position).
        const long long approx = ((long long)v * N_NODES) >> 12;
        int lo = (int)(approx - 8192); if (lo < 0) lo = 0;
        int hi = (int)(approx + 8192); if (hi > N_NODES) hi = N_NODES;

        const int bl = (lo == 0)       ? INT_MIN : id_at(ids32, is64, lo - 1);
        const int bh = (hi == N_NODES) ? INT_MAX : id_at(ids32, is64, hi);
        const int pos1 = kary_probe_pos(lo, hi, sub);
        const bool less1 = id_at(ids32, is64, pos1 - 1) < v;

        if (bl < v && bh >= v) {            // bracket holds (statistically always)
            kary_round(lo, hi, less1, hmask, half_shift);   // fold round 1
            while (hi - lo > 16) {
                const int pos = kary_probe_pos(lo, hi, sub);
                const bool less = id_at(ids32, is64, pos - 1) < v;
                kary_round(lo, hi, less, hmask, half_shift);
            }
            const int pos = lo + sub;
            const bool less = (pos < hi) ? (id_at(ids32, is64, pos) < v) : false;
            const unsigned ball = __ballot_sync(hmask, less);
            res = lo + __popc((ball >> half_shift) & 0xFFFFu);
        } else {                            // correctness fallback: full range
            res = kary_lower_bound(ids32, is64, v, 0, N_NODES, sub, half_shift);
        }
    }
    __syncwarp(FULL);
    const int start = __shfl_sync(FULL, res, 0);
    const int end   = __shfl_sync(FULL, res, 16);
    const int cnt   = end - start;
    const long long base = (long long)start * 2;   // float4 units
    const int n4 = cnt * 2;

    // ---- Phase 2: float4 streaming reduction, unroll 8 + batch tail ----
    float4 acc0 = make_float4(0.f,0.f,0.f,0.f);
    float4 acc1 = make_float4(0.f,0.f,0.f,0.f);
    float4 acc2 = make_float4(0.f,0.f,0.f,0.f);
    float4 acc3 = make_float4(0.f,0.f,0.f,0.f);

    int c = 0;
    while (c + 256 <= n4) {
        const long long p = base + c + lane;
        float4 v0 = ldg_stream(&x4[p      ]);
        float4 v1 = ldg_stream(&x4[p +  32]);
        float4 v2 = ldg_stream(&x4[p +  64]);
        float4 v3 = ldg_stream(&x4[p +  96]);
        float4 v4 = ldg_stream(&x4[p + 128]);
        float4 v5 = ldg_stream(&x4[p + 160]);
        float4 v6 = ldg_stream(&x4[p + 192]);
        float4 v7 = ldg_stream(&x4[p + 224]);
        ACC4(acc0, v0); ACC4(acc1, v1); ACC4(acc2, v2); ACC4(acc3, v3);
        ACC4(acc0, v4); ACC4(acc1, v5); ACC4(acc2, v6); ACC4(acc3, v7);
        c += 256;
    }
    // Batch tail: up to 8 PREDICATED independent loads -> one dependency round.
    {
        const long long p = base + c + lane;
        #pragma unroll
        for (int t = 0; t < 8; t++) {
            if (c + lane + t * 32 < n4) {
                float4 vv = __ldg(&x4[p + t * 32]);
                if (t & 1) { ACC4(acc1, vv); } else { ACC4(acc0, vv); }
            }
        }
    }
    acc0.x += acc1.x + acc2.x + acc3.x;
    acc0.y += acc1.y + acc2.y + acc3.y;
    acc0.z += acc1.z + acc2.z + acc3.z;
    acc0.w += acc1.w + acc2.w + acc3.w;

    // Parity-preserving butterfly: lane 0 -> cols 0-3, lane 1 -> cols 4-7.
    #pragma unroll
    for (int m = 16; m >= 2; m >>= 1) {
        acc0.x += __shfl_xor_sync(FULL, acc0.x, m);
        acc0.y += __shfl_xor_sync(FULL, acc0.y, m);
        acc0.z += __shfl_xor_sync(FULL, acc0.z, m);
        acc0.w += __shfl_xor_sync(FULL, acc0.w, m);
    }

    // ---- Phase 3: broadcast pooled vector via shuffles, fused tiny GEMM ----
    const float inv = (cnt > 0) ? (1.0f / (float)cnt) : 0.0f;
    const float p0 = __shfl_sync(FULL, acc0.x, 0) * inv;
    const float p1 = __shfl_sync(FULL, acc0.y, 0) * inv;
    const float p2 = __shfl_sync(FULL, acc0.z, 0) * inv;
    const float p3 = __shfl_sync(FULL, acc0.w, 0) * inv;
    const float p4 = __shfl_sync(FULL, acc0.x, 1) * inv;
    const float p5 = __shfl_sync(FULL, acc0.y, 1) * inv;
    const float p6 = __shfl_sync(FULL, acc0.z, 1) * inv;
    const float p7 = __shfl_sync(FULL, acc0.w, 1) * inv;

    if (lane < N_CLASSES) {
        const float* w = W + lane * D_FEAT;
        float r = __ldg(&b[lane]);
        r += p0 * __ldg(&w[0]) + p1 * __ldg(&w[1]) + p2 * __ldg(&w[2]) + p3 * __ldg(&w[3]);
        r += p4 * __ldg(&w[4]) + p5 * __ldg(&w[5]) + p6 * __ldg(&w[6]) + p7 * __ldg(&w[7]);
        out[g * N_CLASSES + lane] = r;
    }
}

extern "C" void kernel_launch(void* const* d_in, const int* in_sizes, int n_in,
                              void* d_out, int out_size) {
    // Bind inputs by element count (robust to metadata ordering):
    //   x: 32,000,000 f32 | batch_ids: 4,000,000 | W: 80 | b: 10
    const float* x   = nullptr;
    const void*  ids = nullptr;
    const float* W   = nullptr;
    const float* b   = nullptr;
    for (int i = 0; i < n_in; i++) {
        switch (in_sizes[i]) {
            case N_NODES * D_FEAT:   x   = (const float*)d_in[i]; break;
            case N_NODES:            ids = d_in[i];               break;
            case N_CLASSES * D_FEAT: W   = (const float*)d_in[i]; break;
            case N_CLASSES:          b   = (const float*)d_in[i]; break;
            default: break; // input_ids / attention_mask: unused
        }
    }
    float* out = (float*)d_out;

    fused_pool_gemm_kernel<<<N_BLOCKS, 128>>>(
        (const float4*)x, (const int*)ids, W, b, out);
}